// round 17
// baseline (speedup 1.0000x reference)
#include <cuda_runtime.h>
#include <cuda_bf16.h>
#include <math.h>
#include <stdint.h>

#define NCONF 8192
#define NT 64
#define NX 64
#define GRIDC 888   // 148 SMs * 6 CTAs

// -------- dynamic smem layout (bytes) --------
#define SM_AH     0
#define SM_AL     8192
#define SM_BH     16384
#define SM_BL     24576
#define SM_TOTAL  32768
// stage overlay [0, 8704) = float[4 warps][8 rows][68]

static __device__ __forceinline__ uint32_t smem_u32(const void* p) {
    uint32_t a;
    asm("{ .reg .u64 t; cvta.to.shared.u64 t, %1; cvt.u32.u64 %0, t; }" : "=r"(a) : "l"(p));
    return a;
}
static __device__ __forceinline__ uint32_t pack_hi2(float x, float y) {
    uint32_t r;
    asm("cvt.rn.bf16x2.f32 %0, %1, %2;" : "=r"(r) : "f"(y), "f"(x)); // lo16=bf16(x)
    return r;
}
static __device__ __forceinline__ void cvt_split(float x, float y,
                                                 uint32_t& hi, uint32_t& lo) {
    uint32_t h = pack_hi2(x, y);
    float hx = __uint_as_float(h << 16);
    float hy = __uint_as_float(h & 0xffff0000u);
    lo = pack_hi2(x - hx, y - hy);
    hi = h;
}
static __device__ __forceinline__ void ldsm_x4(uint32_t& r0, uint32_t& r1,
                                               uint32_t& r2, uint32_t& r3, uint32_t addr) {
    asm volatile("ldmatrix.sync.aligned.m8n8.x4.shared.b16 {%0,%1,%2,%3}, [%4];"
                 : "=r"(r0), "=r"(r1), "=r"(r2), "=r"(r3) : "r"(addr));
}
static __device__ __forceinline__ void ldsm_x4t(uint32_t& r0, uint32_t& r1,
                                                uint32_t& r2, uint32_t& r3, uint32_t addr) {
    asm volatile("ldmatrix.sync.aligned.m8n8.x4.trans.shared.b16 {%0,%1,%2,%3}, [%4];"
                 : "=r"(r0), "=r"(r1), "=r"(r2), "=r"(r3) : "r"(addr));
}
// NOTE: non-volatile — pure register op; lets ptxas interleave accumulator chains.
static __device__ __forceinline__ void mma_bf16(float* d, uint32_t a0, uint32_t a1,
                                                uint32_t a2, uint32_t a3,
                                                uint32_t b0, uint32_t b1) {
    asm("mma.sync.aligned.m16n8k16.row.col.f32.bf16.bf16.f32 "
        "{%0,%1,%2,%3}, {%4,%5,%6,%7}, {%8,%9}, {%0,%1,%2,%3};"
        : "+f"(d[0]), "+f"(d[1]), "+f"(d[2]), "+f"(d[3])
        : "r"(a0), "r"(a1), "r"(a2), "r"(a3), "r"(b0), "r"(b1));
}
static __device__ __forceinline__ int t0_reduce(float2 v0, float2 v1, int lane) {
    float b0 = fabsf(v0.x); int j0 = lane;
    float c0 = fabsf(v1.x);
    if (c0 < b0) { b0 = c0; j0 = lane + 32; }
    float b1 = fabsf(v0.y); int j1 = lane;
    float c1 = fabsf(v1.y);
    if (c1 < b1) { b1 = c1; j1 = lane + 32; }
    #pragma unroll
    for (int off = 16; off > 0; off >>= 1) {
        float ob = __shfl_xor_sync(0xffffffffu, b0, off);
        int   oj = __shfl_xor_sync(0xffffffffu, j0, off);
        if (ob < b0 || (ob == b0 && oj < j0)) { b0 = ob; j0 = oj; }
        ob = __shfl_xor_sync(0xffffffffu, b1, off);
        oj = __shfl_xor_sync(0xffffffffu, j1, off);
        if (ob < b1 || (ob == b1 && oj < j1)) { b1 = ob; j1 = oj; }
    }
    return (j0 > j1) ? j1 : j0;
}
static __device__ __forceinline__ void a_stage(char* smem, const float* phic,
                                               int wid, int lane) {
    const float4* g4 = reinterpret_cast<const float4*>(phic);
    #pragma unroll
    for (int s = 0; s < 8; ++s) {
        int idx = wid * 256 + 32 * s + lane;
        float4 v = g4[idx];
        int mrow = idx >> 4;
        int q    = idx & 15;
        uint32_t off = (uint32_t)mrow * 128 +
                       ((uint32_t)((q >> 1) ^ (mrow & 7)) << 4) + ((q & 1) << 3);
        uint32_t hx, lx, hy, ly;
        cvt_split(v.x, v.y, hx, lx);
        cvt_split(v.z, v.w, hy, ly);
        *reinterpret_cast<uint2*>(smem + SM_AH + off) = make_uint2(hx, hy);
        *reinterpret_cast<uint2*>(smem + SM_AL + off) = make_uint2(lx, ly);
    }
}

// ---------------------------------------------------------------------------
__global__ void __launch_bounds__(128, 6) main_kernel(
    const float* __restrict__ phi, const float* __restrict__ W,
    const float* __restrict__ b, float* __restrict__ out, int write_logdet)
{
    extern __shared__ char smem[];
    uint32_t sbase = smem_u32(smem);
    int tid  = threadIdx.x;
    int wid  = tid >> 5;
    int lane = tid & 31;

    if (blockIdx.x == 0) {   // ---------------- LU block ----------------
        float (*A)[65] = reinterpret_cast<float(*)[65]>(smem);
        float* m   = reinterpret_cast<float*>(smem + 16640);
        float* rv  = reinterpret_cast<float*>(smem + 16896);
        int*   ri  = reinterpret_cast<int*>(smem + 16904);
        float* sld = reinterpret_cast<float*>(smem + 16912);

        for (int idx = tid; idx < 64 * 64; idx += 128)
            A[idx >> 6][idx & 63] = W[idx];
        __syncthreads();

        float ld = 0.0f;
        for (int k = 0; k < 64; ++k) {
            if (tid < 64) {
                float v  = (tid >= k) ? fabsf(A[tid][k]) : -1.0f;
                int   vi = tid;
                #pragma unroll
                for (int off = 16; off > 0; off >>= 1) {
                    float ov = __shfl_down_sync(0xffffffffu, v,  off);
                    int   oi = __shfl_down_sync(0xffffffffu, vi, off);
                    if (ov > v) { v = ov; vi = oi; }
                }
                if ((tid & 31) == 0) { rv[tid >> 5] = v; ri[tid >> 5] = vi; }
            }
            __syncthreads();
            int p = (rv[1] > rv[0]) ? ri[1] : ri[0];
            if (tid < 64 && p != k) {
                float t1 = A[k][tid], t2 = A[p][tid];
                A[k][tid] = t2; A[p][tid] = t1;
            }
            __syncthreads();
            float piv = A[k][k];
            if (tid < 64) {
                ld += logf(fabsf(piv));
                if (tid > k) m[tid] = A[tid][k] / piv;
            }
            __syncthreads();
            if (tid < 64 && tid > k) {
                float akj = A[k][tid];
                for (int r = k + 1; r < 64; ++r)
                    A[r][tid] -= m[r] * akj;
            }
            __syncthreads();
        }
        if (write_logdet) {
            if (tid == 0) *sld = ld;
            __syncthreads();
            float val = (float)NT * (*sld);
            float* tail = out + (size_t)NCONF * NT * NX;
            for (int idx = tid; idx < NCONF; idx += 128)
                tail[idx] = val;
        }
        return;
    }

    int i = blockIdx.x - 1;
    const float* phic = phi + (size_t)i * (NT * NX);

    // --- one-time B: W -> bf16 hi/lo, straight layout + swizzle ---
    {
        const float4* w4 = reinterpret_cast<const float4*>(W);
        #pragma unroll
        for (int s = 0; s < 8; ++s) {
            int idx = tid + 128 * s;
            float4 v = w4[idx];
            int vrow = idx >> 4;
            int q    = idx & 15;
            uint32_t off = (uint32_t)vrow * 128 +
                           ((uint32_t)((q >> 1) ^ (vrow & 7)) << 4) + ((q & 1) << 3);
            uint32_t hx, lx, hy, ly;
            cvt_split(v.x, v.y, hx, lx);
            cvt_split(v.z, v.w, hy, ly);
            *reinterpret_cast<uint2*>(smem + SM_BH + off) = make_uint2(hx, hy);
            *reinterpret_cast<uint2*>(smem + SM_BL + off) = make_uint2(lx, ly);
        }
    }

    // --- first-config prologue ---
    int T0;
    {
        float2 u0 = *reinterpret_cast<const float2*>(phic + (size_t)lane * NX);
        float2 u1 = *reinterpret_cast<const float2*>(phic + (size_t)(lane + 32) * NX);
        T0 = t0_reduce(u0, u1, lane);
    }
    a_stage(smem, phic, wid, lane);
    __syncthreads();

    int mrel = (lane & 7) + ((lane >> 3) & 1) * 8;
    int csel = (lane >> 4) & 1;
    int mm   = 16 * wid + mrel;
    int qrow = lane >> 2;
    int qcol = (lane & 3) * 2;

    for (;;) {
        int offs = (64 - T0) & 63;

        float d[8][4];
        #pragma unroll
        for (int nt = 0; nt < 8; ++nt)
            #pragma unroll
            for (int e = 0; e < 4; ++e) d[nt][e] = 0.0f;

        #pragma unroll
        for (int kk = 0; kk < 4; ++kk) {
            uint32_t co = (uint32_t)((kk * 2 + csel) ^ (mm & 7)) << 4;
            uint32_t rowoff = (uint32_t)mm * 128 + co;
            uint32_t ahi[4], alo[4];
            ldsm_x4(ahi[0], ahi[1], ahi[2], ahi[3], sbase + SM_AH + rowoff);
            ldsm_x4(alo[0], alo[1], alo[2], alo[3], sbase + SM_AL + rowoff);

            int vphys = (kk * 16 + mrel + T0) & 63;   // rolled W row
            uint32_t bro = (uint32_t)vphys * 128;
            int vb = vphys & 7;

            // np-pairs: load B for two n-strips (hi+lo), then 12 MMAs
            // round-robin over 4 accumulator chains (same-d gap = 4).
            #pragma unroll
            for (int npp = 0; npp < 2; ++npp) {
                int np0 = 2 * npp, np1 = np0 + 1;
                uint32_t bc0 = (uint32_t)((np0 * 2 + csel) ^ vb) << 4;
                uint32_t bc1 = (uint32_t)((np1 * 2 + csel) ^ vb) << 4;
                uint32_t bh0[4], bh1[4], bl0[4], bl1[4];
                ldsm_x4t(bh0[0], bh0[1], bh0[2], bh0[3], sbase + SM_BH + bro + bc0);
                ldsm_x4t(bh1[0], bh1[1], bh1[2], bh1[3], sbase + SM_BH + bro + bc1);
                ldsm_x4t(bl0[0], bl0[1], bl0[2], bl0[3], sbase + SM_BL + bro + bc0);
                ldsm_x4t(bl1[0], bl1[1], bl1[2], bl1[3], sbase + SM_BL + bro + bc1);

                mma_bf16(d[2 * np0],     ahi[0], ahi[1], ahi[2], ahi[3], bh0[0], bh0[1]);
                mma_bf16(d[2 * np0 + 1], ahi[0], ahi[1], ahi[2], ahi[3], bh0[2], bh0[3]);
                mma_bf16(d[2 * np1],     ahi[0], ahi[1], ahi[2], ahi[3], bh1[0], bh1[1]);
                mma_bf16(d[2 * np1 + 1], ahi[0], ahi[1], ahi[2], ahi[3], bh1[2], bh1[3]);

                mma_bf16(d[2 * np0],     alo[0], alo[1], alo[2], alo[3], bh0[0], bh0[1]);
                mma_bf16(d[2 * np0 + 1], alo[0], alo[1], alo[2], alo[3], bh0[2], bh0[3]);
                mma_bf16(d[2 * np1],     alo[0], alo[1], alo[2], alo[3], bh1[0], bh1[1]);
                mma_bf16(d[2 * np1 + 1], alo[0], alo[1], alo[2], alo[3], bh1[2], bh1[3]);

                mma_bf16(d[2 * np0],     ahi[0], ahi[1], ahi[2], ahi[3], bl0[0], bl0[1]);
                mma_bf16(d[2 * np0 + 1], ahi[0], ahi[1], ahi[2], ahi[3], bl0[2], bl0[3]);
                mma_bf16(d[2 * np1],     ahi[0], ahi[1], ahi[2], ahi[3], bl1[0], bl1[1]);
                mma_bf16(d[2 * np1 + 1], ahi[0], ahi[1], ahi[2], ahi[3], bl1[2], bl1[3]);
            }
        }
        __syncthreads();   // (1) all warps done reading A (stage overlays A)

        int inext = i + GRIDC;
        bool more = (inext < NCONF);
        const float* phin = phi + (size_t)inext * (NT * NX);

        // --- two-phase epilogue: stage 8 rows (stride 68), flush, repeat ---
        float* st = reinterpret_cast<float*>(smem) + wid * (8 * 68);
        float* obase = out + (size_t)i * (NT * NX) + (size_t)(16 * wid) * NX;

        #pragma unroll
        for (int nt = 0; nt < 8; ++nt) {
            int jb = 8 * nt + qcol;
            float2 bias = __ldg(reinterpret_cast<const float2*>(b + jb));
            st[qrow * 68 + ((jb + offs) & 63)]     = d[nt][0] + bias.x;
            st[qrow * 68 + ((jb + 1 + offs) & 63)] = d[nt][1] + bias.y;
        }
        float2 w0, w1;
        if (more) {
            w0 = *reinterpret_cast<const float2*>(phin + (size_t)lane * NX);
            w1 = *reinterpret_cast<const float2*>(phin + (size_t)(lane + 32) * NX);
        }
        __syncwarp();
        #pragma unroll
        for (int it = 0; it < 4; ++it) {
            int r  = it * 2 + (lane >> 4);
            int c4 = (lane & 15) * 4;
            float4 v = *reinterpret_cast<const float4*>(st + r * 68 + c4);
            *reinterpret_cast<float4*>(obase + (size_t)r * NX + c4) = v;
        }
        __syncwarp();
        #pragma unroll
        for (int nt = 0; nt < 8; ++nt) {
            int jb = 8 * nt + qcol;
            float2 bias = __ldg(reinterpret_cast<const float2*>(b + jb));
            st[qrow * 68 + ((jb + offs) & 63)]     = d[nt][2] + bias.x;
            st[qrow * 68 + ((jb + 1 + offs) & 63)] = d[nt][3] + bias.y;
        }
        __syncwarp();
        #pragma unroll
        for (int it = 0; it < 4; ++it) {
            int r  = it * 2 + (lane >> 4);
            int c4 = (lane & 15) * 4;
            float4 v = *reinterpret_cast<const float4*>(st + r * 68 + c4);
            *reinterpret_cast<float4*>(obase + (size_t)(r + 8) * NX + c4) = v;
        }

        if (!more) break;

        T0 = t0_reduce(w0, w1, lane);
        __syncthreads();   // (2) all flushes done -> A/stage region writable

        a_stage(smem, phin, wid, lane);
        __syncwarp();
        i = inext;
    }
}

// ---------------------------------------------------------------------------
extern "C" void kernel_launch(void* const* d_in, const int* in_sizes, int n_in,
                              void* d_out, int out_size) {
    const float* phi = nullptr;
    const float* W   = nullptr;
    const float* b   = nullptr;
    for (int k = 0; k < n_in; ++k) {
        if      (in_sizes[k] == NCONF * NT * NX) phi = (const float*)d_in[k];
        else if (in_sizes[k] == NX * NX)         W   = (const float*)d_in[k];
        else if (in_sizes[k] == NX)              b   = (const float*)d_in[k];
    }
    float* out = (float*)d_out;
    int write_logdet = (out_size >= NCONF * NT * NX + NCONF) ? 1 : 0;

    cudaFuncSetAttribute(main_kernel, cudaFuncAttributeMaxDynamicSharedMemorySize, SM_TOTAL);
    main_kernel<<<GRIDC + 1, 128, SM_TOTAL>>>(phi, W, b, out, write_logdet);
}